// round 8
// baseline (speedup 1.0000x reference)
#include <cuda_runtime.h>
#include <cuda_bf16.h>
#include <cstdint>

#define LEN   2048
#define VOCAB 50000
#define EDIM  256          // embedding dim (E) — reference: V,E,HID,T = 50000,256,512,12
#define HDIM  256          // per-direction hidden (H = HID/2)
#define G4    1024         // 4*H gate rows
#define NTAG  12
#define START_TAG 10
#define STOP_TAG  11
#define NEGV  (-10000.0f)

#define NREG   40                         // W_hh columns in registers
#define NSMEM  52                         // W_hh columns in shared memory
#define SMEM_FLOATS (NSMEM * G4 + 256 + G4)
#define SMEM_BYTES  (SMEM_FLOATS * 4)     // 218,112 B

// ---------------- scratch (static device globals; no allocation) ----------------
__device__ float g_wt[2][HDIM][G4];       // W_hh^T per direction (2 MB)
__device__ float g_xg[2][LEN][G4];        // x@W_ih^T + b         (16 MB)
__device__ float g_h[LEN][2 * HDIM];      // concatenated hf|hb   (4 MB)
__device__ float g_feats[LEN][NTAG];      // emission features

// ---------------- helpers ----------------
__device__ __forceinline__ float fsig_(float x) {
    return __fdividef(1.f, 1.f + __expf(-x));
}
__device__ __forceinline__ float ftanh_(float x) {
    return 1.f - __fdividef(2.f, __expf(2.f * x) + 1.f);
}

// ================= Kernel 0: transpose W_hh -> g_wt (both directions) ==============
// W_hh: [1024 gate rows][256 h cols] -> g_wt: [256 h cols][1024 gate rows]
__global__ void __launch_bounds__(256) transpose_whh(
    const float* __restrict__ wf, const float* __restrict__ wb)
{
    long i = (long)blockIdx.x * blockDim.x + threadIdx.x;    // 0..524287
    if (i < 262144) {
        int r = (int)(i >> 8), c = (int)(i & 255);
        g_wt[0][c][r] = wf[i];
    } else if (i < 524288) {
        long k = i - 262144;
        int r = (int)(k >> 8), c = (int)(k & 255);
        g_wt[1][c][r] = wb[k];
    }
}

// ================= Kernel 1: xg = embed[sentence] @ W_ih^T + (b_ih + b_hh) =========
// grid (LEN/64, G4/64, 2), block 256. Tile 64t x 64row, K = EDIM = 256, chunks of 32.
__global__ void __launch_bounds__(256) xg_gemm(
    const int* __restrict__ sent, const float* __restrict__ embed,
    const float* __restrict__ w_f, const float* __restrict__ w_b,
    const float* __restrict__ bi_f, const float* __restrict__ bh_f,
    const float* __restrict__ bi_b, const float* __restrict__ bh_b)
{
    const int dir = blockIdx.z;
    const float* __restrict__ W = dir ? w_b : w_f;   // [1024][EDIM=256]
    const int t0 = blockIdx.x * 64;
    const int r0 = blockIdx.y * 64;

    __shared__ __align__(16) float xs[32][68];
    __shared__ __align__(16) float ws[32][68];
    __shared__ int   sidx[64];

    const int tid = threadIdx.x;
    if (tid < 64) {
        int v = sent[t0 + tid];
        v = v < 0 ? 0 : (v >= VOCAB ? VOCAB - 1 : v);
        sidx[tid] = v;
    }
    __syncthreads();

    float acc[4][4];
#pragma unroll
    for (int i = 0; i < 4; i++)
#pragma unroll
        for (int j = 0; j < 4; j++) acc[i][j] = 0.f;

    const int ty = tid >> 4;
    const int tx = tid & 15;

    for (int k0 = 0; k0 < EDIM; k0 += 32) {
#pragma unroll
        for (int i = 0; i < 8; i++) {
            int idx = i * 256 + tid;
            int a = idx >> 5, kk = idx & 31;
            xs[kk][a] = embed[(long)sidx[a] * EDIM + k0 + kk];
            ws[kk][a] = W[(long)(r0 + a) * EDIM + k0 + kk];
        }
        __syncthreads();
#pragma unroll
        for (int kk = 0; kk < 32; kk++) {
            float4 xv = *(const float4*)&xs[kk][ty * 4];
            float4 wv = *(const float4*)&ws[kk][tx * 4];
            float xa[4] = {xv.x, xv.y, xv.z, xv.w};
            float wa[4] = {wv.x, wv.y, wv.z, wv.w};
#pragma unroll
            for (int i = 0; i < 4; i++)
#pragma unroll
                for (int j = 0; j < 4; j++) acc[i][j] += xa[i] * wa[j];
        }
        __syncthreads();
    }

    const float* __restrict__ bi = dir ? bi_b : bi_f;
    const float* __restrict__ bh = dir ? bh_b : bh_f;
#pragma unroll
    for (int j = 0; j < 4; j++) {
        int row = r0 + tx * 4 + j;
        float b = bi[row] + bh[row];
#pragma unroll
        for (int i = 0; i < 4; i++) {
            int t = t0 + ty * 4 + i;
            g_xg[dir][t][row] = acc[i][j] + b;
        }
    }
}

// ================= Kernel 2: LSTM recurrence — ONE CTA per direction ===============
// grid (2), block 256. Thread tid owns gate rows 4*tid..4*tid+3.
// W_hh columns: [0,NREG) registers, [NREG,NREG+NSMEM) smem, rest streamed from L2
// via transposed g_wt. No inter-CTA communication. Gate order (PyTorch): i,f,g,o.
__global__ void __launch_bounds__(256, 1)
lstm_single(const float* __restrict__ whh_f, const float* __restrict__ whh_b)
{
    extern __shared__ float dsm[];
    float* wsm  = dsm;                    // [NSMEM][1024] col-major slices of W_hh^T
    float* hbuf = dsm + NSMEM * G4;       // [256]
    float* pre  = hbuf + 256;             // [1024]

    const int dir = blockIdx.x;
    const int tid = threadIdx.x;
    const float* __restrict__ W  = dir ? whh_b : whh_f;    // [1024][256]
    const float* __restrict__ WT = &g_wt[dir][0][0];       // [256][1024]

    // register-resident weight columns [0, NREG)
    float wr[4][NREG];
#pragma unroll
    for (int j = 0; j < 4; j++) {
        const float4* wp = (const float4*)(W + (long)(4 * tid + j) * HDIM);
#pragma unroll
        for (int cc = 0; cc < NREG / 4; cc++) {
            float4 v = wp[cc];
            wr[j][4 * cc + 0] = v.x; wr[j][4 * cc + 1] = v.y;
            wr[j][4 * cc + 2] = v.z; wr[j][4 * cc + 3] = v.w;
        }
    }
    // smem-resident weight columns [NREG, NREG+NSMEM)
    for (int idx = tid; idx < NSMEM * G4; idx += 256) {
        int c = idx >> 10, r = idx & 1023;
        wsm[idx] = WT[(long)(NREG + c) * G4 + r];
    }
    hbuf[tid] = 0.f;
    __syncthreads();

    float cstate = 0.f;
    const float* __restrict__ xg = &g_xg[dir][0][0];

    for (int step = 0; step < LEN; step++) {
        const int t = dir ? (LEN - 1 - step) : step;

        float4 xv = *(const float4*)&xg[(long)t * G4 + 4 * tid];
        float acc0 = xv.x, acc1 = xv.y, acc2 = xv.z, acc3 = xv.w;

#pragma unroll
        for (int c = 0; c < NREG; c++) {
            float hc = hbuf[c];
            acc0 += wr[0][c] * hc; acc1 += wr[1][c] * hc;
            acc2 += wr[2][c] * hc; acc3 += wr[3][c] * hc;
        }
#pragma unroll 4
        for (int c = 0; c < NSMEM; c++) {
            float hc = hbuf[NREG + c];
            float4 wv = *(const float4*)&wsm[c * G4 + 4 * tid];
            acc0 += wv.x * hc; acc1 += wv.y * hc;
            acc2 += wv.z * hc; acc3 += wv.w * hc;
        }
#pragma unroll 4
        for (int c = NREG + NSMEM; c < HDIM; c++) {
            float hc = hbuf[c];
            float4 wv = *(const float4*)&WT[(long)c * G4 + 4 * tid];
            acc0 += wv.x * hc; acc1 += wv.y * hc;
            acc2 += wv.z * hc; acc3 += wv.w * hc;
        }

        pre[4 * tid + 0] = acc0;
        pre[4 * tid + 1] = acc1;
        pre[4 * tid + 2] = acc2;
        pre[4 * tid + 3] = acc3;
        __syncthreads();

        {
            float gi = pre[tid];
            float gf = pre[256 + tid];
            float gg = pre[512 + tid];
            float go = pre[768 + tid];
            float ii = fsig_(gi), ff = fsig_(gf), oo = fsig_(go);
            cstate = ff * cstate + ii * ftanh_(gg);
            float h = oo * ftanh_(cstate);
            hbuf[tid] = h;
            g_h[t][dir * HDIM + tid] = h;
        }
        __syncthreads();
    }
}

// ================= Kernel 3: feats = h @ w_out^T + b_out =================
// h: [L, 2H=512], w_out: [12, 512]
__global__ void __launch_bounds__(256) feats_kernel(
    const float* __restrict__ w_out, const float* __restrict__ b_out)
{
    __shared__ __align__(16) float hs[16][2 * HDIM];
    const int t0 = blockIdx.x * 16;
    const int tid = threadIdx.x;

    const float* src = &g_h[t0][0];
#pragma unroll
    for (int i = 0; i < 32; i++) {
        int idx = i * 256 + tid;              // 8192 floats
        ((float*)hs)[idx] = src[idx];
    }
    __syncthreads();

    if (tid < 192) {
        int tt = tid / NTAG, tg = tid % NTAG;
        const float4* h4 = (const float4*)hs[tt];
        const float4* w4 = (const float4*)(w_out + (long)tg * (2 * HDIM));
        float s = 0.f;
#pragma unroll 8
        for (int k = 0; k < (2 * HDIM) / 4; k++) {
            float4 a = h4[k];
            float4 b = w4[k];
            s += a.x * b.x + a.y * b.y + a.z * b.z + a.w * b.w;
        }
        g_feats[t0 + tt][tg] = s + b_out[tg];
    }
}

// ================= Kernel 4: Viterbi forward + backtrack (1 warp) =================
__global__ void __launch_bounds__(32) viterbi_kernel(
    const float* __restrict__ trans, float* __restrict__ out, int out_cap)
{
    __shared__ unsigned char bp[LEN][NTAG];
    const int lane = threadIdx.x;
    const bool act = lane < NTAG;
    const int ln = act ? lane : (NTAG - 1);      // clamp: speculated loads stay in-bounds

    float Trow[NTAG];
#pragma unroll
    for (int j = 0; j < NTAG; j++)
        Trow[j] = trans[ln * NTAG + j];

    float v = (lane == START_TAG) ? 0.f : NEGV;
    float feat = g_feats[0][ln];

    for (int t = 0; t < LEN; t++) {
        int tn = (t + 1 < LEN) ? (t + 1) : t;
        float featn = g_feats[tn][ln];
        float best = -3.4e38f;
        int bj = 0;
#pragma unroll
        for (int j = 0; j < NTAG; j++) {
            float vj = __shfl_sync(0xffffffffu, v, j);
            float cand = vj + Trow[j];
            if (cand > best) { best = cand; bj = j; }
        }
        v = best + feat;
        if (act) bp[t][lane] = (unsigned char)bj;
        feat = featn;
    }

    float tv = act ? (v + trans[STOP_TAG * NTAG + ln]) : -3.4e38f;
    int ti = lane;
#pragma unroll
    for (int off = 16; off >= 1; off >>= 1) {
        float ov = __shfl_xor_sync(0xffffffffu, tv, off);
        int   oi = __shfl_xor_sync(0xffffffffu, ti, off);
        if (ov > tv || (ov == tv && oi < ti)) { tv = ov; ti = oi; }
    }

    if (lane == 0) {
        if (out_cap > 0) out[0] = tv;
        int tag = ti;
        for (int t = LEN - 1; t >= 0; t--) {
            if (1 + t < out_cap) out[1 + t] = (float)tag;
            tag = bp[t][tag];
        }
    }
}

// ================= launch =================
extern "C" void kernel_launch(void* const* d_in, const int* in_sizes, int n_in,
                              void* d_out, int out_size)
{
    const int*   sentence = (const int*)  d_in[0];   // [2048] int32
    const float* embed    = (const float*)d_in[1];   // [50000, 256]
    const float* w_ih_f   = (const float*)d_in[2];   // [1024, 256]
    const float* w_hh_f   = (const float*)d_in[3];   // [1024, 256]
    const float* b_ih_f   = (const float*)d_in[4];   // [1024]
    const float* b_hh_f   = (const float*)d_in[5];   // [1024]
    const float* w_ih_b   = (const float*)d_in[6];
    const float* w_hh_b   = (const float*)d_in[7];
    const float* b_ih_b   = (const float*)d_in[8];
    const float* b_hh_b   = (const float*)d_in[9];
    const float* w_out    = (const float*)d_in[10];  // [12, 512]
    const float* b_out    = (const float*)d_in[11];  // [12]
    const float* trans    = (const float*)d_in[12];  // [12, 12]

    int out_cap = out_size < (LEN + 1) ? out_size : (LEN + 1);

    cudaFuncSetAttribute(lstm_single,
                         cudaFuncAttributeMaxDynamicSharedMemorySize, SMEM_BYTES);

    transpose_whh<<<2048, 256>>>(w_hh_f, w_hh_b);
    xg_gemm<<<dim3(LEN / 64, G4 / 64, 2), 256>>>(sentence, embed,
                                                 w_ih_f, w_ih_b,
                                                 b_ih_f, b_hh_f, b_ih_b, b_hh_b);
    lstm_single<<<2, 256, SMEM_BYTES>>>(w_hh_f, w_hh_b);
    feats_kernel<<<LEN / 16, 256>>>(w_out, b_out);
    viterbi_kernel<<<1, 32>>>(trans, (float*)d_out, out_cap);
}

// round 9
// speedup vs baseline: 3.3760x; 3.3760x over previous
#include <cuda_runtime.h>
#include <cuda_bf16.h>
#include <cstdint>

#define LEN   2048
#define VOCAB 50000
#define EDIM  256          // embedding dim E (reference: V,E,HID,T = 50000,256,512,12)
#define HDIM  256          // per-direction hidden H = HID/2
#define G4    1024         // 4*H gate rows
#define NTAG  12
#define START_TAG 10
#define STOP_TAG  11
#define NEGV  (-10000.0f)

// ---------------- scratch (static device globals; no allocation) ----------------
__device__ float g_xg[2][LEN][G4];     // x@W_ih^T + (b_ih+b_hh) per direction (16 MB)
__device__ float g_h[LEN][2 * HDIM];   // concatenated hf|hb                    (4 MB)
__device__ float g_feats[LEN][NTAG];   // emission features

// ---------------- helpers ----------------
__device__ __forceinline__ uint32_t smem_u32(const void* p) {
    return (uint32_t)__cvta_generic_to_shared(p);
}
__device__ __forceinline__ float fsig_(float x) {
    return __fdividef(1.f, 1.f + __expf(-x));
}
__device__ __forceinline__ float ftanh_(float x) {
    return 1.f - __fdividef(2.f, __expf(2.f * x) + 1.f);
}

// ================= Kernel 1: xg = embed[sentence] @ W_ih^T + (b_ih + b_hh) =========
// grid (LEN/64, G4/64, 2), block 256. Tile 64t x 64row, K = EDIM = 256 in chunks of 32.
__global__ void __launch_bounds__(256) xg_gemm(
    const int* __restrict__ sent, const float* __restrict__ embed,
    const float* __restrict__ w_f, const float* __restrict__ w_b,
    const float* __restrict__ bi_f, const float* __restrict__ bh_f,
    const float* __restrict__ bi_b, const float* __restrict__ bh_b)
{
    const int dir = blockIdx.z;
    const float* __restrict__ W = dir ? w_b : w_f;   // [1024][256]
    const int t0 = blockIdx.x * 64;
    const int r0 = blockIdx.y * 64;

    __shared__ __align__(16) float xs[32][68];
    __shared__ __align__(16) float ws[32][68];
    __shared__ int   sidx[64];

    const int tid = threadIdx.x;
    if (tid < 64) {
        int v = sent[t0 + tid];
        v = v < 0 ? 0 : (v >= VOCAB ? VOCAB - 1 : v);
        sidx[tid] = v;
    }
    __syncthreads();

    float acc[4][4];
#pragma unroll
    for (int i = 0; i < 4; i++)
#pragma unroll
        for (int j = 0; j < 4; j++) acc[i][j] = 0.f;

    const int ty = tid >> 4;
    const int tx = tid & 15;

    for (int k0 = 0; k0 < EDIM; k0 += 32) {
#pragma unroll
        for (int i = 0; i < 8; i++) {
            int idx = i * 256 + tid;
            int a = idx >> 5, kk = idx & 31;
            xs[kk][a] = embed[(long)sidx[a] * EDIM + k0 + kk];
            ws[kk][a] = W[(long)(r0 + a) * EDIM + k0 + kk];
        }
        __syncthreads();
#pragma unroll
        for (int kk = 0; kk < 32; kk++) {
            float4 xv = *(const float4*)&xs[kk][ty * 4];
            float4 wv = *(const float4*)&ws[kk][tx * 4];
            float xa[4] = {xv.x, xv.y, xv.z, xv.w};
            float wa[4] = {wv.x, wv.y, wv.z, wv.w};
#pragma unroll
            for (int i = 0; i < 4; i++)
#pragma unroll
                for (int j = 0; j < 4; j++) acc[i][j] += xa[i] * wa[j];
        }
        __syncthreads();
    }

    const float* __restrict__ bi = dir ? bi_b : bi_f;
    const float* __restrict__ bh = dir ? bh_b : bh_f;
#pragma unroll
    for (int j = 0; j < 4; j++) {
        int row = r0 + tx * 4 + j;
        float b = bi[row] + bh[row];
#pragma unroll
        for (int i = 0; i < 4; i++) {
            int t = t0 + ty * 4 + i;
            g_xg[dir][t][row] = acc[i][j] + b;
        }
    }
}

// ================= Kernel 2: bidirectional LSTM recurrence (cluster DSMEM) =========
// grid 16 CTAs = 2 clusters of 8 (cluster 0 = forward, cluster 1 = backward).
// Each CTA owns 32 h-elements (128 gate rows). W_hh slice lives in REGISTERS
// (64 floats/thread x 512 threads). h exchanged each step via DSMEM multicast
// stores + one cluster barrier. Gate order (PyTorch): i, f, g, o.
__global__ void __cluster_dims__(8, 1, 1) __launch_bounds__(512, 1)
lstm_kernel(const float* __restrict__ whh_f, const float* __restrict__ whh_b)
{
    const int dir = blockIdx.x >> 3;
    unsigned rank;
    asm("mov.u32 %0, %%cluster_ctarank;" : "=r"(rank));
    const float* __restrict__ Whh = dir ? whh_b : whh_f;

    const int tid  = threadIdx.x;     // 0..511
    const int g    = tid >> 2;        // local gate 0..127
    const int p    = tid & 3;         // 64-element segment of the 256-dot
    const int u    = g >> 5;          // gate type 0..3 (i,f,g,o)
    const int kloc = g & 31;
    const int row  = u * HDIM + (int)rank * 32 + kloc;   // row in W_hh [1024,256]

    // weights -> registers
    float w[64];
    {
        const float4* wp = (const float4*)(Whh + (long)row * HDIM + p * 64);
#pragma unroll
        for (int i = 0; i < 16; i++) {
            float4 v = wp[i];
            w[4 * i + 0] = v.x; w[4 * i + 1] = v.y;
            w[4 * i + 2] = v.z; w[4 * i + 3] = v.w;
        }
    }

    __shared__ __align__(16) float hbuf[2][HDIM];
    __shared__ __align__(16) float pre[128];
    if (tid < HDIM) hbuf[0][tid] = 0.f;
    __syncthreads();

    // DSMEM target addresses of this CTA's 32-element h slot (used by tid < 32)
    const int slot = (int)rank * 32 + (tid & 31);
    const uint32_t h_l0 = smem_u32(&hbuf[0][slot]);
    const uint32_t h_l1 = smem_u32(&hbuf[1][slot]);

    float c = 0.f;
    const float* __restrict__ xg = &g_xg[dir][0][0];
    int buf = 0;

    // all CTAs' smem init complete cluster-wide before any DSMEM traffic
    asm volatile("barrier.cluster.arrive.aligned;" ::: "memory");
    asm volatile("barrier.cluster.wait.aligned;"   ::: "memory");

    for (int step = 0; step < LEN; step++) {
        const int t = dir ? (LEN - 1 - step) : step;

        float xv = 0.f;
        if (p == 0) xv = __ldg(&xg[(long)t * G4 + row]);   // issued early, consumed late

        // 64-element partial dot from local smem h
        float s = 0.f;
        const float4* hp = (const float4*)&hbuf[buf][p * 64];
#pragma unroll
        for (int i = 0; i < 16; i++) {
            float4 hv = hp[i];
            s += w[4 * i + 0] * hv.x;
            s += w[4 * i + 1] * hv.y;
            s += w[4 * i + 2] * hv.z;
            s += w[4 * i + 3] * hv.w;
        }
        s += __shfl_xor_sync(0xffffffffu, s, 1);
        s += __shfl_xor_sync(0xffffffffu, s, 2);
        if (p == 0) pre[g] = s + xv;
        __syncthreads();

        if (tid < 32) {
            float gi = pre[tid];
            float gf = pre[32 + tid];
            float gg = pre[64 + tid];
            float go = pre[96 + tid];
            float ii = fsig_(gi), ff = fsig_(gf), oo = fsig_(go);
            c = ff * c + ii * ftanh_(gg);
            float h = oo * ftanh_(c);

            uint32_t dst = (buf ^ 1) ? h_l1 : h_l0;
#pragma unroll
            for (int peer = 0; peer < 8; peer++) {
                uint32_t rem;
                asm volatile("mapa.shared::cluster.u32 %0, %1, %2;"
                             : "=r"(rem) : "r"(dst), "r"(peer));
                asm volatile("st.shared::cluster.f32 [%0], %1;"
                             :: "r"(rem), "f"(h) : "memory");
            }
            g_h[t][dir * HDIM + slot] = h;
        }

        // release my DSMEM writes / acquire peers' writes for next step
        asm volatile("barrier.cluster.arrive.aligned;" ::: "memory");
        asm volatile("barrier.cluster.wait.aligned;"   ::: "memory");
        buf ^= 1;
    }
}

// ================= Kernel 3: feats = h @ w_out^T + b_out =================
__global__ void __launch_bounds__(256) feats_kernel(
    const float* __restrict__ w_out, const float* __restrict__ b_out)
{
    __shared__ __align__(16) float hs[16][2 * HDIM];
    const int t0 = blockIdx.x * 16;
    const int tid = threadIdx.x;

    const float* src = &g_h[t0][0];
#pragma unroll
    for (int i = 0; i < 32; i++) {
        int idx = i * 256 + tid;              // 8192 floats
        ((float*)hs)[idx] = src[idx];
    }
    __syncthreads();

    if (tid < 192) {
        int tt = tid / NTAG, tg = tid % NTAG;
        const float4* h4 = (const float4*)hs[tt];
        const float4* w4 = (const float4*)(w_out + (long)tg * (2 * HDIM));
        float s = 0.f;
#pragma unroll 8
        for (int k = 0; k < (2 * HDIM) / 4; k++) {
            float4 a = h4[k];
            float4 b = w4[k];
            s += a.x * b.x + a.y * b.y + a.z * b.z + a.w * b.w;
        }
        g_feats[t0 + tt][tg] = s + b_out[tg];
    }
}

// ================= Kernel 4: Viterbi forward + backtrack (1 warp) =================
__global__ void __launch_bounds__(32) viterbi_kernel(
    const float* __restrict__ trans, float* __restrict__ out, int out_cap)
{
    __shared__ unsigned char bp[LEN][NTAG];
    const int lane = threadIdx.x;
    const bool act = lane < NTAG;
    const int ln = act ? lane : (NTAG - 1);      // clamp: speculated loads stay in-bounds

    float Trow[NTAG];
#pragma unroll
    for (int j = 0; j < NTAG; j++)
        Trow[j] = trans[ln * NTAG + j];

    float v = (lane == START_TAG) ? 0.f : NEGV;
    float feat = g_feats[0][ln];

    for (int t = 0; t < LEN; t++) {
        int tn = (t + 1 < LEN) ? (t + 1) : t;
        float featn = g_feats[tn][ln];
        float best = -3.4e38f;
        int bj = 0;
#pragma unroll
        for (int j = 0; j < NTAG; j++) {
            float vj = __shfl_sync(0xffffffffu, v, j);
            float cand = vj + Trow[j];
            if (cand > best) { best = cand; bj = j; }
        }
        v = best + feat;
        if (act) bp[t][lane] = (unsigned char)bj;
        feat = featn;
    }

    float tv = act ? (v + trans[STOP_TAG * NTAG + ln]) : -3.4e38f;
    int ti = lane;
#pragma unroll
    for (int off = 16; off >= 1; off >>= 1) {
        float ov = __shfl_xor_sync(0xffffffffu, tv, off);
        int   oi = __shfl_xor_sync(0xffffffffu, ti, off);
        if (ov > tv || (ov == tv && oi < ti)) { tv = ov; ti = oi; }
    }

    if (lane == 0) {
        if (out_cap > 0) out[0] = tv;
        int tag = ti;
        for (int t = LEN - 1; t >= 0; t--) {
            if (1 + t < out_cap) out[1 + t] = (float)tag;
            tag = bp[t][tag];
        }
    }
}

// ================= launch =================
extern "C" void kernel_launch(void* const* d_in, const int* in_sizes, int n_in,
                              void* d_out, int out_size)
{
    const int*   sentence = (const int*)  d_in[0];   // [2048] int32
    const float* embed    = (const float*)d_in[1];   // [50000, 256]
    const float* w_ih_f   = (const float*)d_in[2];   // [1024, 256]
    const float* w_hh_f   = (const float*)d_in[3];   // [1024, 256]
    const float* b_ih_f   = (const float*)d_in[4];   // [1024]
    const float* b_hh_f   = (const float*)d_in[5];   // [1024]
    const float* w_ih_b   = (const float*)d_in[6];
    const float* w_hh_b   = (const float*)d_in[7];
    const float* b_ih_b   = (const float*)d_in[8];
    const float* b_hh_b   = (const float*)d_in[9];
    const float* w_out    = (const float*)d_in[10];  // [12, 512]
    const float* b_out    = (const float*)d_in[11];  // [12]
    const float* trans    = (const float*)d_in[12];  // [12, 12]

    int out_cap = out_size < (LEN + 1) ? out_size : (LEN + 1);

    xg_gemm<<<dim3(LEN / 64, G4 / 64, 2), 256>>>(sentence, embed,
                                                 w_ih_f, w_ih_b,
                                                 b_ih_f, b_hh_f, b_ih_b, b_hh_b);
    lstm_kernel<<<16, 512>>>(w_hh_f, w_hh_b);
    feats_kernel<<<LEN / 16, 256>>>(w_out, b_out);
    viterbi_kernel<<<1, 32>>>(trans, (float*)d_out, out_cap);
}

// round 10
// speedup vs baseline: 5.2618x; 1.5586x over previous
#include <cuda_runtime.h>
#include <cuda_bf16.h>
#include <cstdint>

#define LEN   2048
#define VOCAB 50000
#define EDIM  256          // embedding dim E (reference: V,E,HID,T = 50000,256,512,12)
#define HDIM  256          // per-direction hidden H = HID/2
#define G4    1024         // 4*H gate rows
#define NTAG  12
#define START_TAG 10
#define STOP_TAG  11
#define NEGV  (-10000.0f)

// ---------------- scratch (static device globals; no allocation) ----------------
__device__ float g_xg[2][LEN][G4];     // x@W_ih^T + (b_ih+b_hh) per direction (16 MB)
__device__ float g_h[LEN][2 * HDIM];   // concatenated hf|hb                    (4 MB)
__device__ float g_feats[LEN][NTAG];   // emission features

// ---------------- helpers ----------------
__device__ __forceinline__ uint32_t smem_u32(const void* p) {
    return (uint32_t)__cvta_generic_to_shared(p);
}
__device__ __forceinline__ float fsig_(float x) {
    return __fdividef(1.f, 1.f + __expf(-x));
}
__device__ __forceinline__ float ftanh_(float x) {
    return 1.f - __fdividef(2.f, __expf(2.f * x) + 1.f);
}
__device__ __forceinline__ unsigned long long packf2_(float lo, float hi) {
    unsigned long long r;
    asm("mov.b64 %0, {%1, %2};" : "=l"(r) : "f"(lo), "f"(hi));
    return r;
}
__device__ __forceinline__ void unpackf2_(unsigned long long v, float& lo, float& hi) {
    asm("mov.b64 {%0, %1}, %2;" : "=f"(lo), "=f"(hi) : "l"(v));
}
__device__ __forceinline__ unsigned long long fma2_(
    unsigned long long a, unsigned long long b, unsigned long long c) {
    unsigned long long r;
    asm("fma.rn.f32x2 %0, %1, %2, %3;" : "=l"(r) : "l"(a), "l"(b), "l"(c));
    return r;
}

// ================= Kernel 1: xg = embed[sentence] @ W_ih^T + (b_ih + b_hh) =========
// grid (LEN/64, G4/64, 2), block 256. Tile 64t x 64row, K = EDIM = 256 in chunks of 32.
__global__ void __launch_bounds__(256) xg_gemm(
    const int* __restrict__ sent, const float* __restrict__ embed,
    const float* __restrict__ w_f, const float* __restrict__ w_b,
    const float* __restrict__ bi_f, const float* __restrict__ bh_f,
    const float* __restrict__ bi_b, const float* __restrict__ bh_b)
{
    const int dir = blockIdx.z;
    const float* __restrict__ W = dir ? w_b : w_f;   // [1024][256]
    const int t0 = blockIdx.x * 64;
    const int r0 = blockIdx.y * 64;

    __shared__ __align__(16) float xs[32][68];
    __shared__ __align__(16) float ws[32][68];
    __shared__ int   sidx[64];

    const int tid = threadIdx.x;
    if (tid < 64) {
        int v = sent[t0 + tid];
        v = v < 0 ? 0 : (v >= VOCAB ? VOCAB - 1 : v);
        sidx[tid] = v;
    }
    __syncthreads();

    float acc[4][4];
#pragma unroll
    for (int i = 0; i < 4; i++)
#pragma unroll
        for (int j = 0; j < 4; j++) acc[i][j] = 0.f;

    const int ty = tid >> 4;
    const int tx = tid & 15;

    for (int k0 = 0; k0 < EDIM; k0 += 32) {
#pragma unroll
        for (int i = 0; i < 8; i++) {
            int idx = i * 256 + tid;
            int a = idx >> 5, kk = idx & 31;
            xs[kk][a] = embed[(long)sidx[a] * EDIM + k0 + kk];
            ws[kk][a] = W[(long)(r0 + a) * EDIM + k0 + kk];
        }
        __syncthreads();
#pragma unroll
        for (int kk = 0; kk < 32; kk++) {
            float4 xv = *(const float4*)&xs[kk][ty * 4];
            float4 wv = *(const float4*)&ws[kk][tx * 4];
            float xa[4] = {xv.x, xv.y, xv.z, xv.w};
            float wa[4] = {wv.x, wv.y, wv.z, wv.w};
#pragma unroll
            for (int i = 0; i < 4; i++)
#pragma unroll
                for (int j = 0; j < 4; j++) acc[i][j] += xa[i] * wa[j];
        }
        __syncthreads();
    }

    const float* __restrict__ bi = dir ? bi_b : bi_f;
    const float* __restrict__ bh = dir ? bh_b : bh_f;
#pragma unroll
    for (int j = 0; j < 4; j++) {
        int row = r0 + tx * 4 + j;
        float b = bi[row] + bh[row];
#pragma unroll
        for (int i = 0; i < 4; i++) {
            int t = t0 + ty * 4 + i;
            g_xg[dir][t][row] = acc[i][j] + b;
        }
    }
}

// ================= Kernel 2: bidirectional LSTM recurrence (cluster DSMEM) =========
// grid 16 CTAs = 2 clusters of 8 (cluster 0 = forward, cluster 1 = backward).
// Layout: tid = k*16 + seg. Thread (k, seg) computes, for local h-index k
// (global kg = rank*32 + k), the partial dots of ALL FOUR gate rows
// (u*256 + kg, u = i,f,g,o) over h columns [seg*16, seg*16+16), using f32x2
// packed FMA with weights in registers. 16-lane shfl reduce; lane seg==0 does
// the activation for its h-index and multicasts h to all 8 CTAs via DSMEM.
__global__ void __cluster_dims__(8, 1, 1) __launch_bounds__(512, 1)
lstm_kernel(const float* __restrict__ whh_f, const float* __restrict__ whh_b)
{
    const int dir = blockIdx.x >> 3;
    unsigned rank;
    asm("mov.u32 %0, %%cluster_ctarank;" : "=r"(rank));
    const float* __restrict__ Whh = dir ? whh_b : whh_f;

    const int tid = threadIdx.x;      // 0..511
    const int k   = tid >> 4;         // local h-index 0..31
    const int seg = tid & 15;         // 16-column segment of the 256-dot
    const int kg  = (int)rank * 32 + k;   // global h-index 0..255

    // weights -> registers, packed f32x2: wd[u][i] = (W[row][c], W[row][c+1])
    unsigned long long wd[4][8];
#pragma unroll
    for (int u = 0; u < 4; u++) {
        const float4* wp = (const float4*)(Whh + (long)(u * HDIM + kg) * HDIM + seg * 16);
#pragma unroll
        for (int i = 0; i < 4; i++) {
            float4 v = wp[i];
            wd[u][2 * i + 0] = packf2_(v.x, v.y);
            wd[u][2 * i + 1] = packf2_(v.z, v.w);
        }
    }

    __shared__ __align__(16) float hbuf[2][HDIM];
    if (tid < HDIM) hbuf[0][tid] = 0.f;
    __syncthreads();

    // DSMEM local addresses of this thread's h slot (used by seg==0 threads)
    const uint32_t h_l0 = smem_u32(&hbuf[0][kg]);
    const uint32_t h_l1 = smem_u32(&hbuf[1][kg]);

    float cstate = 0.f;
    const float* __restrict__ xg = &g_xg[dir][0][0];
    int buf = 0;

    // all CTAs' smem init complete cluster-wide before any DSMEM traffic
    asm volatile("barrier.cluster.arrive.aligned;" ::: "memory");
    asm volatile("barrier.cluster.wait.aligned;"   ::: "memory");

    for (int step = 0; step < LEN; step++) {
        const int t = dir ? (LEN - 1 - step) : step;

        // prefetch this step's x-gate values early (consumed after the reduce)
        float xv0 = 0.f, xv1 = 0.f, xv2 = 0.f, xv3 = 0.f;
        if (seg == 0) {
            const float* xr = &xg[(long)t * G4 + kg];
            xv0 = __ldg(xr);
            xv1 = __ldg(xr + HDIM);
            xv2 = __ldg(xr + 2 * HDIM);
            xv3 = __ldg(xr + 3 * HDIM);
        }

        // packed partial dots: 4 gates x 8 f32x2 FMAs
        unsigned long long acc0 = 0ull, acc1 = 0ull, acc2 = 0ull, acc3 = 0ull;
        const ulonglong2* hp = (const ulonglong2*)&hbuf[buf][seg * 16];
#pragma unroll
        for (int i = 0; i < 4; i++) {
            ulonglong2 hv = hp[i];
            acc0 = fma2_(wd[0][2 * i], hv.x, acc0);
            acc1 = fma2_(wd[1][2 * i], hv.x, acc1);
            acc2 = fma2_(wd[2][2 * i], hv.x, acc2);
            acc3 = fma2_(wd[3][2 * i], hv.x, acc3);
            acc0 = fma2_(wd[0][2 * i + 1], hv.y, acc0);
            acc1 = fma2_(wd[1][2 * i + 1], hv.y, acc1);
            acc2 = fma2_(wd[2][2 * i + 1], hv.y, acc2);
            acc3 = fma2_(wd[3][2 * i + 1], hv.y, acc3);
        }
        float lo, hi, s0, s1, s2, s3;
        unpackf2_(acc0, lo, hi); s0 = lo + hi;
        unpackf2_(acc1, lo, hi); s1 = lo + hi;
        unpackf2_(acc2, lo, hi); s2 = lo + hi;
        unpackf2_(acc3, lo, hi); s3 = lo + hi;

        // reduce over the 16 seg lanes (xor masks < 16 stay within each half-warp)
#pragma unroll
        for (int m = 1; m < 16; m <<= 1) {
            s0 += __shfl_xor_sync(0xffffffffu, s0, m);
            s1 += __shfl_xor_sync(0xffffffffu, s1, m);
            s2 += __shfl_xor_sync(0xffffffffu, s2, m);
            s3 += __shfl_xor_sync(0xffffffffu, s3, m);
        }

        if (seg == 0) {
            float gi = s0 + xv0;
            float gf = s1 + xv1;
            float gg = s2 + xv2;
            float go = s3 + xv3;
            float ii = fsig_(gi), ff = fsig_(gf), oo = fsig_(go);
            cstate = ff * cstate + ii * ftanh_(gg);
            float h = oo * ftanh_(cstate);

            uint32_t dst = (buf ^ 1) ? h_l1 : h_l0;
#pragma unroll
            for (int peer = 0; peer < 8; peer++) {
                uint32_t rem;
                asm volatile("mapa.shared::cluster.u32 %0, %1, %2;"
                             : "=r"(rem) : "r"(dst), "r"(peer));
                asm volatile("st.shared::cluster.f32 [%0], %1;"
                             :: "r"(rem), "f"(h) : "memory");
            }
            g_h[t][dir * HDIM + kg] = h;
        }

        // release my DSMEM writes / acquire peers' writes for next step
        asm volatile("barrier.cluster.arrive.aligned;" ::: "memory");
        asm volatile("barrier.cluster.wait.aligned;"   ::: "memory");
        buf ^= 1;
    }
}

// ================= Kernel 3: feats = h @ w_out^T + b_out =================
__global__ void __launch_bounds__(256) feats_kernel(
    const float* __restrict__ w_out, const float* __restrict__ b_out)
{
    __shared__ __align__(16) float hs[16][2 * HDIM];
    const int t0 = blockIdx.x * 16;
    const int tid = threadIdx.x;

    const float* src = &g_h[t0][0];
#pragma unroll
    for (int i = 0; i < 32; i++) {
        int idx = i * 256 + tid;              // 8192 floats
        ((float*)hs)[idx] = src[idx];
    }
    __syncthreads();

    if (tid < 192) {
        int tt = tid / NTAG, tg = tid % NTAG;
        const float4* h4 = (const float4*)hs[tt];
        const float4* w4 = (const float4*)(w_out + (long)tg * (2 * HDIM));
        float s = 0.f;
#pragma unroll 8
        for (int kk = 0; kk < (2 * HDIM) / 4; kk++) {
            float4 a = h4[kk];
            float4 b = w4[kk];
            s += a.x * b.x + a.y * b.y + a.z * b.z + a.w * b.w;
        }
        g_feats[t0 + tt][tg] = s + b_out[tg];
    }
}

// ================= Kernel 4: Viterbi forward + backtrack (1 warp) =================
__global__ void __launch_bounds__(32) viterbi_kernel(
    const float* __restrict__ trans, float* __restrict__ out, int out_cap)
{
    __shared__ unsigned char bp[LEN][NTAG];
    const int lane = threadIdx.x;
    const bool act = lane < NTAG;
    const int ln = act ? lane : (NTAG - 1);      // clamp: speculated loads stay in-bounds

    float Trow[NTAG];
#pragma unroll
    for (int j = 0; j < NTAG; j++)
        Trow[j] = trans[ln * NTAG + j];

    float v = (lane == START_TAG) ? 0.f : NEGV;
    float feat = g_feats[0][ln];

    for (int t = 0; t < LEN; t++) {
        int tn = (t + 1 < LEN) ? (t + 1) : t;
        float featn = g_feats[tn][ln];
        float best = -3.4e38f;
        int bj = 0;
#pragma unroll
        for (int j = 0; j < NTAG; j++) {
            float vj = __shfl_sync(0xffffffffu, v, j);
            float cand = vj + Trow[j];
            if (cand > best) { best = cand; bj = j; }
        }
        v = best + feat;
        if (act) bp[t][lane] = (unsigned char)bj;
        feat = featn;
    }

    float tv = act ? (v + trans[STOP_TAG * NTAG + ln]) : -3.4e38f;
    int ti = lane;
#pragma unroll
    for (int off = 16; off >= 1; off >>= 1) {
        float ov = __shfl_xor_sync(0xffffffffu, tv, off);
        int   oi = __shfl_xor_sync(0xffffffffu, ti, off);
        if (ov > tv || (ov == tv && oi < ti)) { tv = ov; ti = oi; }
    }

    if (lane == 0) {
        if (out_cap > 0) out[0] = tv;
        int tag = ti;
        for (int t = LEN - 1; t >= 0; t--) {
            if (1 + t < out_cap) out[1 + t] = (float)tag;
            tag = bp[t][tag];
        }
    }
}

// ================= launch =================
extern "C" void kernel_launch(void* const* d_in, const int* in_sizes, int n_in,
                              void* d_out, int out_size)
{
    const int*   sentence = (const int*)  d_in[0];   // [2048] int32
    const float* embed    = (const float*)d_in[1];   // [50000, 256]
    const float* w_ih_f   = (const float*)d_in[2];   // [1024, 256]
    const float* w_hh_f   = (const float*)d_in[3];   // [1024, 256]
    const float* b_ih_f   = (const float*)d_in[4];   // [1024]
    const float* b_hh_f   = (const float*)d_in[5];   // [1024]
    const float* w_ih_b   = (const float*)d_in[6];
    const float* w_hh_b   = (const float*)d_in[7];
    const float* b_ih_b   = (const float*)d_in[8];
    const float* b_hh_b   = (const float*)d_in[9];
    const float* w_out    = (const float*)d_in[10];  // [12, 512]
    const float* b_out    = (const float*)d_in[11];  // [12]
    const float* trans    = (const float*)d_in[12];  // [12, 12]

    int out_cap = out_size < (LEN + 1) ? out_size : (LEN + 1);

    xg_gemm<<<dim3(LEN / 64, G4 / 64, 2), 256>>>(sentence, embed,
                                                 w_ih_f, w_ih_b,
                                                 b_ih_f, b_hh_f, b_ih_b, b_hh_b);
    lstm_kernel<<<16, 512>>>(w_hh_f, w_hh_b);
    feats_kernel<<<LEN / 16, 256>>>(w_out, b_out);
    viterbi_kernel<<<1, 32>>>(trans, (float*)d_out, out_cap);
}

// round 11
// speedup vs baseline: 5.6666x; 1.0769x over previous
#include <cuda_runtime.h>
#include <cuda_bf16.h>
#include <cstdint>

#define LEN   2048
#define VOCAB 50000
#define EDIM  256          // embedding dim E (reference: V,E,HID,T = 50000,256,512,12)
#define HDIM  256          // per-direction hidden H = HID/2
#define G4    1024         // 4*H gate rows
#define NTAG  12
#define START_TAG 10
#define STOP_TAG  11
#define NEGV  (-10000.0f)

// ---------------- scratch (static device globals; no allocation) ----------------
__device__ float g_xg[2][LEN][G4];     // x@W_ih^T + (b_ih+b_hh) per direction (16 MB)
__device__ float g_h[LEN][2 * HDIM];   // concatenated hf|hb                    (4 MB)
__device__ float g_feats[LEN][NTAG];   // emission features

// ---------------- helpers ----------------
__device__ __forceinline__ uint32_t smem_u32(const void* p) {
    return (uint32_t)__cvta_generic_to_shared(p);
}
__device__ __forceinline__ float fsig_(float x) {
    return __fdividef(1.f, 1.f + __expf(-x));
}
__device__ __forceinline__ float ftanh_(float x) {
    return 1.f - __fdividef(2.f, __expf(2.f * x) + 1.f);
}
__device__ __forceinline__ unsigned long long packf2_(float lo, float hi) {
    unsigned long long r;
    asm("mov.b64 %0, {%1, %2};" : "=l"(r) : "f"(lo), "f"(hi));
    return r;
}
__device__ __forceinline__ void unpackf2_(unsigned long long v, float& lo, float& hi) {
    asm("mov.b64 {%0, %1}, %2;" : "=f"(lo), "=f"(hi) : "l"(v));
}
__device__ __forceinline__ unsigned long long fma2_(
    unsigned long long a, unsigned long long b, unsigned long long c) {
    unsigned long long r;
    asm("fma.rn.f32x2 %0, %1, %2, %3;" : "=l"(r) : "l"(a), "l"(b), "l"(c));
    return r;
}

#define MBARRIER_INIT(mbar_addr, count) \
    asm volatile("mbarrier.init.shared.b64 [%0], %1;" \
                 :: "r"((uint32_t)(mbar_addr)), "r"((uint32_t)(count)) : "memory")

// Remote arrive: map local mbar address into target CTA's SMEM, then arrive.
#define MBARRIER_ARRIVE_CLUSTER(local_mbar_addr, target_rank) \
    asm volatile( \
        "{\n\t" \
        ".reg .b32 remAddr32;\n\t" \
        "mapa.shared::cluster.u32 remAddr32, %0, %1;\n\t" \
        "mbarrier.arrive.shared::cluster.b64 _, [remAddr32];\n\t" \
        "}" \
        :: "r"((uint32_t)(local_mbar_addr)), "r"((uint32_t)(target_rank)) : "memory")

#define MBARRIER_WAIT_PARITY(mbar_smem_addr, phase_parity) do { \
    uint32_t _mbar = (uint32_t)(mbar_smem_addr); \
    uint32_t _parity = (uint32_t)(phase_parity); \
    uint32_t _done; \
    asm volatile( \
        "{\n\t" \
        ".reg .pred p;\n\t" \
        "mbarrier.try_wait.parity.acquire.cta.shared::cta.b64 p, [%1], %2;\n\t" \
        "selp.b32 %0, 1, 0, p;\n\t" \
        "}" \
        : "=r"(_done) : "r"(_mbar), "r"(_parity) : "memory"); \
    if (!_done) { \
        asm volatile( \
            "{\n\t" \
            ".reg .pred P1;\n\t" \
            "WAIT_LOOP_%=:\n\t" \
            "mbarrier.try_wait.parity.acquire.cta.shared::cta.b64 P1, [%0], %1, 0x989680;\n\t" \
            "@P1 bra.uni WAIT_DONE_%=;\n\t" \
            "bra.uni WAIT_LOOP_%=;\n\t" \
            "WAIT_DONE_%=:\n\t" \
            "}" \
            :: "r"(_mbar), "r"(_parity) : "memory"); \
    } \
} while(0)

// ================= Kernel 1: xg = embed[sentence] @ W_ih^T + (b_ih + b_hh) =========
__global__ void __launch_bounds__(256) xg_gemm(
    const int* __restrict__ sent, const float* __restrict__ embed,
    const float* __restrict__ w_f, const float* __restrict__ w_b,
    const float* __restrict__ bi_f, const float* __restrict__ bh_f,
    const float* __restrict__ bi_b, const float* __restrict__ bh_b)
{
    const int dir = blockIdx.z;
    const float* __restrict__ W = dir ? w_b : w_f;   // [1024][256]
    const int t0 = blockIdx.x * 64;
    const int r0 = blockIdx.y * 64;

    __shared__ __align__(16) float xs[32][68];
    __shared__ __align__(16) float ws[32][68];
    __shared__ int   sidx[64];

    const int tid = threadIdx.x;
    if (tid < 64) {
        int v = sent[t0 + tid];
        v = v < 0 ? 0 : (v >= VOCAB ? VOCAB - 1 : v);
        sidx[tid] = v;
    }
    __syncthreads();

    float acc[4][4];
#pragma unroll
    for (int i = 0; i < 4; i++)
#pragma unroll
        for (int j = 0; j < 4; j++) acc[i][j] = 0.f;

    const int ty = tid >> 4;
    const int tx = tid & 15;

    for (int k0 = 0; k0 < EDIM; k0 += 32) {
#pragma unroll
        for (int i = 0; i < 8; i++) {
            int idx = i * 256 + tid;
            int a = idx >> 5, kk = idx & 31;
            xs[kk][a] = embed[(long)sidx[a] * EDIM + k0 + kk];
            ws[kk][a] = W[(long)(r0 + a) * EDIM + k0 + kk];
        }
        __syncthreads();
#pragma unroll
        for (int kk = 0; kk < 32; kk++) {
            float4 xv = *(const float4*)&xs[kk][ty * 4];
            float4 wv = *(const float4*)&ws[kk][tx * 4];
            float xa[4] = {xv.x, xv.y, xv.z, xv.w};
            float wa[4] = {wv.x, wv.y, wv.z, wv.w};
#pragma unroll
            for (int i = 0; i < 4; i++)
#pragma unroll
                for (int j = 0; j < 4; j++) acc[i][j] += xa[i] * wa[j];
        }
        __syncthreads();
    }

    const float* __restrict__ bi = dir ? bi_b : bi_f;
    const float* __restrict__ bh = dir ? bh_b : bh_f;
#pragma unroll
    for (int j = 0; j < 4; j++) {
        int row = r0 + tx * 4 + j;
        float b = bi[row] + bh[row];
#pragma unroll
        for (int i = 0; i < 4; i++) {
            int t = t0 + ty * 4 + i;
            g_xg[dir][t][row] = acc[i][j] + b;
        }
    }
}

// ================= Kernel 2: bidirectional LSTM recurrence (mbarrier ping-pong) ====
// grid 16 CTAs = 2 clusters of 8. tid = k*16 + seg; thread (k, seg) computes the
// 4 gate partial dots of global h-index kg = rank*32+k over columns [seg*16,+16)
// in f32x2. Per step: try_wait(mbar[s&3]) -> dot hbuf[s&1] -> reduce -> seg==0
// activation -> DSMEM multicast h into hbuf[(s+1)&1] -> syncthreads ->
// fence.acq_rel.cluster -> 8 remote arrives at mbar[(s+1)&3].
__global__ void __cluster_dims__(8, 1, 1) __launch_bounds__(512, 1)
lstm_kernel(const float* __restrict__ whh_f, const float* __restrict__ whh_b)
{
    const int dir = blockIdx.x >> 3;
    unsigned rank;
    asm("mov.u32 %0, %%cluster_ctarank;" : "=r"(rank));
    const float* __restrict__ Whh = dir ? whh_b : whh_f;

    const int tid = threadIdx.x;      // 0..511
    const int k   = tid >> 4;         // local h-index 0..31
    const int seg = tid & 15;         // 16-column segment
    const int kg  = (int)rank * 32 + k;

    // weights -> registers (32 f32x2 = 64 regs)
    unsigned long long wd[4][8];
#pragma unroll
    for (int u = 0; u < 4; u++) {
        const float4* wp = (const float4*)(Whh + (long)(u * HDIM + kg) * HDIM + seg * 16);
#pragma unroll
        for (int i = 0; i < 4; i++) {
            float4 v = wp[i];
            wd[u][2 * i + 0] = packf2_(v.x, v.y);
            wd[u][2 * i + 1] = packf2_(v.z, v.w);
        }
    }

    __shared__ __align__(16) float hbuf[2][HDIM];
    __shared__ __align__(8) unsigned long long mbar[4];
    if (tid < HDIM) hbuf[0][tid] = 0.f;
    if (tid == 0) {
#pragma unroll
        for (int i = 0; i < 4; i++)
            MBARRIER_INIT(smem_u32(&mbar[i]), 8);
    }
    __syncthreads();

    // all CTAs: smem + mbar init visible cluster-wide before any DSMEM traffic
    asm volatile("barrier.cluster.arrive.aligned;" ::: "memory");
    asm volatile("barrier.cluster.wait.aligned;"   ::: "memory");

    const uint32_t mb0 = smem_u32(&mbar[0]);
    const uint32_t mb1 = smem_u32(&mbar[1]);
    const uint32_t mb2 = smem_u32(&mbar[2]);
    const uint32_t mb3 = smem_u32(&mbar[3]);
    const uint32_t h_l0 = smem_u32(&hbuf[0][kg]);
    const uint32_t h_l1 = smem_u32(&hbuf[1][kg]);

    // step-0 arrivals (h=0 already local everywhere; cluster barrier ordered it)
    if (tid == 0) {
#pragma unroll
        for (int peer = 0; peer < 8; peer++)
            MBARRIER_ARRIVE_CLUSTER(mb0, peer);
    }

    float cstate = 0.f;
    const float* __restrict__ xg = &g_xg[dir][0][0];

    for (int step = 0; step < LEN; step++) {
        const int t = dir ? (LEN - 1 - step) : step;

        // prefetch this step's x-gate values (no h dependency)
        float xv0 = 0.f, xv1 = 0.f, xv2 = 0.f, xv3 = 0.f;
        if (seg == 0) {
            const float* xr = &xg[(long)t * G4 + kg];
            xv0 = __ldg(xr);
            xv1 = __ldg(xr + HDIM);
            xv2 = __ldg(xr + 2 * HDIM);
            xv3 = __ldg(xr + 3 * HDIM);
        }

        // wait for this step's h (8 producer arrivals)
        uint32_t mb = (step & 3) == 0 ? mb0 : (step & 3) == 1 ? mb1
                     : (step & 3) == 2 ? mb2 : mb3;
        MBARRIER_WAIT_PARITY(mb, (step >> 2) & 1);

        const int buf = step & 1;
        unsigned long long acc0 = 0ull, acc1 = 0ull, acc2 = 0ull, acc3 = 0ull;
        const ulonglong2* hp = (const ulonglong2*)&hbuf[buf][seg * 16];
#pragma unroll
        for (int i = 0; i < 4; i++) {
            ulonglong2 hv = hp[i];
            acc0 = fma2_(wd[0][2 * i], hv.x, acc0);
            acc1 = fma2_(wd[1][2 * i], hv.x, acc1);
            acc2 = fma2_(wd[2][2 * i], hv.x, acc2);
            acc3 = fma2_(wd[3][2 * i], hv.x, acc3);
            acc0 = fma2_(wd[0][2 * i + 1], hv.y, acc0);
            acc1 = fma2_(wd[1][2 * i + 1], hv.y, acc1);
            acc2 = fma2_(wd[2][2 * i + 1], hv.y, acc2);
            acc3 = fma2_(wd[3][2 * i + 1], hv.y, acc3);
        }
        float lo, hi, s0, s1, s2, s3;
        unpackf2_(acc0, lo, hi); s0 = lo + hi;
        unpackf2_(acc1, lo, hi); s1 = lo + hi;
        unpackf2_(acc2, lo, hi); s2 = lo + hi;
        unpackf2_(acc3, lo, hi); s3 = lo + hi;

#pragma unroll
        for (int m = 1; m < 16; m <<= 1) {
            s0 += __shfl_xor_sync(0xffffffffu, s0, m);
            s1 += __shfl_xor_sync(0xffffffffu, s1, m);
            s2 += __shfl_xor_sync(0xffffffffu, s2, m);
            s3 += __shfl_xor_sync(0xffffffffu, s3, m);
        }

        if (seg == 0) {
            float gi = s0 + xv0;
            float gf = s1 + xv1;
            float gg = s2 + xv2;
            float go = s3 + xv3;
            float ii = fsig_(gi), ff = fsig_(gf), oo = fsig_(go);
            cstate = ff * cstate + ii * ftanh_(gg);
            float h = oo * ftanh_(cstate);

            if (step != LEN - 1) {
                uint32_t dst = (buf ^ 1) ? h_l1 : h_l0;
#pragma unroll
                for (int peer = 0; peer < 8; peer++) {
                    uint32_t rem;
                    asm volatile("mapa.shared::cluster.u32 %0, %1, %2;"
                                 : "=r"(rem) : "r"(dst), "r"(peer));
                    asm volatile("st.shared::cluster.f32 [%0], %1;"
                                 :: "r"(rem), "f"(h) : "memory");
                }
            }
            g_h[t][dir * HDIM + kg] = h;
        }

        if (step != LEN - 1) {
            __syncthreads();                       // all 32 producers' stores issued
            if (tid == 0) {
                asm volatile("fence.acq_rel.cluster;" ::: "memory");
                uint32_t mbn = ((step + 1) & 3) == 0 ? mb0 : ((step + 1) & 3) == 1 ? mb1
                              : ((step + 1) & 3) == 2 ? mb2 : mb3;
#pragma unroll
                for (int peer = 0; peer < 8; peer++)
                    MBARRIER_ARRIVE_CLUSTER(mbn, peer);
            }
        }
    }
}

// ================= Kernel 3: feats = h @ w_out^T + b_out =================
__global__ void __launch_bounds__(256) feats_kernel(
    const float* __restrict__ w_out, const float* __restrict__ b_out)
{
    __shared__ __align__(16) float hs[16][2 * HDIM];
    const int t0 = blockIdx.x * 16;
    const int tid = threadIdx.x;

    const float* src = &g_h[t0][0];
#pragma unroll
    for (int i = 0; i < 32; i++) {
        int idx = i * 256 + tid;
        ((float*)hs)[idx] = src[idx];
    }
    __syncthreads();

    if (tid < 192) {
        int tt = tid / NTAG, tg = tid % NTAG;
        const float4* h4 = (const float4*)hs[tt];
        const float4* w4 = (const float4*)(w_out + (long)tg * (2 * HDIM));
        float s = 0.f;
#pragma unroll 8
        for (int kk = 0; kk < (2 * HDIM) / 4; kk++) {
            float4 a = h4[kk];
            float4 b = w4[kk];
            s += a.x * b.x + a.y * b.y + a.z * b.z + a.w * b.w;
        }
        g_feats[t0 + tt][tg] = s + b_out[tg];
    }
}

// ================= Kernel 4: Viterbi forward + backtrack (1 warp, replicated v) ====
// v replicated as 12 registers in every lane. Lane l computes v_new[l] via a pure
// fmaxf tree (short critical path); first-max argmax recovered by an equality
// scan OFF the critical path; 12 shfl broadcasts rebuild replicated v.
__global__ void __launch_bounds__(32) viterbi_kernel(
    const float* __restrict__ trans, float* __restrict__ out, int out_cap)
{
    __shared__ unsigned char bp[LEN][NTAG];
    const int lane = threadIdx.x;
    const bool act = lane < NTAG;
    const int ln = act ? lane : (NTAG - 1);      // clamp: speculated loads stay in-bounds

    float Trow[NTAG];
#pragma unroll
    for (int j = 0; j < NTAG; j++)
        Trow[j] = trans[ln * NTAG + j];

    float v[NTAG];
#pragma unroll
    for (int j = 0; j < NTAG; j++)
        v[j] = (j == START_TAG) ? 0.f : NEGV;

    float feat = g_feats[0][ln];

    for (int t = 0; t < LEN; t++) {
        int tn = (t + 1 < LEN) ? (t + 1) : t;
        float featn = g_feats[tn][ln];

        float cand[NTAG];
#pragma unroll
        for (int j = 0; j < NTAG; j++) cand[j] = v[j] + Trow[j];

        // max tree (critical path: depth 4 of FMNMX)
        float m0 = fmaxf(cand[0], cand[1]);
        float m1 = fmaxf(cand[2], cand[3]);
        float m2 = fmaxf(cand[4], cand[5]);
        float m3 = fmaxf(cand[6], cand[7]);
        float m4 = fmaxf(cand[8], cand[9]);
        float m5 = fmaxf(cand[10], cand[11]);
        float n0 = fmaxf(m0, m1);
        float n1 = fmaxf(m2, m3);
        float n2 = fmaxf(m4, m5);
        float best = fmaxf(fmaxf(n0, n1), n2);

        float vl = best + feat;

        // first-max argmax, off the v critical path
        int bj = NTAG - 1;
#pragma unroll
        for (int j = NTAG - 1; j >= 0; j--)
            if (cand[j] == best) bj = j;
        if (act) bp[t][lane] = (unsigned char)bj;

        // rebuild replicated v
#pragma unroll
        for (int j = 0; j < NTAG; j++)
            v[j] = __shfl_sync(0xffffffffu, vl, j);

        feat = featn;
    }

    float tv = act ? (v[ln] + trans[STOP_TAG * NTAG + ln]) : -3.4e38f;
    int ti = lane;
#pragma unroll
    for (int off = 16; off >= 1; off >>= 1) {
        float ov = __shfl_xor_sync(0xffffffffu, tv, off);
        int   oi = __shfl_xor_sync(0xffffffffu, ti, off);
        if (ov > tv || (ov == tv && oi < ti)) { tv = ov; ti = oi; }
    }

    if (lane == 0) {
        if (out_cap > 0) out[0] = tv;
        int tag = ti;
        for (int t = LEN - 1; t >= 0; t--) {
            if (1 + t < out_cap) out[1 + t] = (float)tag;
            tag = bp[t][tag];
        }
    }
}

// ================= launch =================
extern "C" void kernel_launch(void* const* d_in, const int* in_sizes, int n_in,
                              void* d_out, int out_size)
{
    const int*   sentence = (const int*)  d_in[0];
    const float* embed    = (const float*)d_in[1];
    const float* w_ih_f   = (const float*)d_in[2];
    const float* w_hh_f   = (const float*)d_in[3];
    const float* b_ih_f   = (const float*)d_in[4];
    const float* b_hh_f   = (const float*)d_in[5];
    const float* w_ih_b   = (const float*)d_in[6];
    const float* w_hh_b   = (const float*)d_in[7];
    const float* b_ih_b   = (const float*)d_in[8];
    const float* b_hh_b   = (const float*)d_in[9];
    const float* w_out    = (const float*)d_in[10];
    const float* b_out    = (const float*)d_in[11];
    const float* trans    = (const float*)d_in[12];

    int out_cap = out_size < (LEN + 1) ? out_size : (LEN + 1);

    xg_gemm<<<dim3(LEN / 64, G4 / 64, 2), 256>>>(sentence, embed,
                                                 w_ih_f, w_ih_b,
                                                 b_ih_f, b_hh_f, b_ih_b, b_hh_b);
    lstm_kernel<<<16, 512>>>(w_hh_f, w_hh_b);
    feats_kernel<<<LEN / 16, 256>>>(w_out, b_out);
    viterbi_kernel<<<1, 32>>>(trans, (float*)d_out, out_cap);
}